// round 7
// baseline (speedup 1.0000x reference)
#include <cuda_runtime.h>

#define FS 4096
#define FT 4096
#define NPTS (FS * 8)            // 32768 sample points
#define NPE  (NPTS + FS)         // + 4096 src barycenters = 36864
#define TPB 256
#define RTPB 128
#define SLICES 16
#define SL 256                   // candidates per slice
#define CH 8                     // chunk size
#define NCH (SL / CH)            // 32 chunks per slice
#define SRC_PG (NPTS / (RTPB * 2))   // 128 point-groups (256 pts each)
#define TGT_PG (NPE  / (RTPB * 2))   // 144 point-groups
#define MRG_BLK (NPTS / TPB)         // 128
#define FSUM_BLK (FS / TPB)          // 16

typedef unsigned long long u64;

// Scratch (allocation-free: __device__ globals)
__device__ float4 g_src_bc[FS];        // xyz, w = 0.5*|bc|^2 (candidate form)
__device__ float4 g_tgt_bc[FT];        // xyz, w = 0.5*|bc|^2
__device__ float4 g_pts[NPE];          // xyz, w = |p|^2 (full norm)
__device__ float  g_be[SLICES][NPTS][6];
__device__ int    g_bi[SLICES][NPTS][6];
__device__ float  g_mteh[SLICES][NPE];
__device__ float  g_fwd_partial[FSUM_BLK];
__device__ float  g_rev_partial[MRG_BLK];

// ---- packed f32x2 helpers (sm_103a) ---------------------------------------
__device__ __forceinline__ u64 pk2(float a, float b) {
    u64 r; asm("mov.b64 %0,{%1,%2};" : "=l"(r) : "f"(a), "f"(b)); return r;
}
__device__ __forceinline__ u64 fma2(u64 a, u64 b, u64 c) {
    u64 d; asm("fma.rn.f32x2 %0,%1,%2,%3;" : "=l"(d) : "l"(a), "l"(b), "l"(c)); return d;
}
__device__ __forceinline__ void upk2(u64 d, float& x, float& y) {
    asm("mov.b64 {%0,%1},%2;" : "=f"(x), "=f"(y) : "l"(d));
}

// ascending insert, strict < keeps earlier (lower-index) candidate on ties
__device__ __forceinline__ void try_insert(float e, int j, float be[6], int bi[6]) {
    if (e < be[5]) {
        be[5] = e; bi[5] = j;
        #pragma unroll
        for (int k = 5; k > 0; --k) {
            if (be[k] < be[k-1]) {
                float te = be[k]; be[k] = be[k-1]; be[k-1] = te;
                int   ti = bi[k]; bi[k] = bi[k-1]; bi[k-1] = ti;
            }
        }
    }
}

// Pack SL candidates (pair-interleaved) from g[off..off+SL) into smem.
__device__ __forceinline__ void load_packed_slice(ulonglong2* s, const float4* g,
                                                  int off, int tid) {
    for (int t = tid; t < SL/2; t += RTPB) {
        float4 a = g[off + 2*t], b = g[off + 2*t + 1];
        ulonglong2 u0, u1;
        u0.x = pk2(a.x, b.x); u0.y = pk2(a.y, b.y);
        u1.x = pk2(a.z, b.z); u1.y = pk2(a.w, b.w);
        s[2*t]   = u0;
        s[2*t+1] = u1;
    }
}

// ---------------------------------------------------------------------------
// Kernel 1: barycenters + sampled points (+ barycenters-as-points)
// ---------------------------------------------------------------------------
__global__ void prep_kernel(const float* __restrict__ sv, const int* __restrict__ sf,
                            const float* __restrict__ tv, const int* __restrict__ tf,
                            const float* __restrict__ r1u, const float* __restrict__ r2u) {
    int i = blockIdx.x * blockDim.x + threadIdx.x;
    if (i < FS) {
        int a = sf[3*i+0], b = sf[3*i+1], c = sf[3*i+2];
        float x = (sv[3*a+0] + sv[3*b+0] + sv[3*c+0]) * (1.0f/3.0f);
        float y = (sv[3*a+1] + sv[3*b+1] + sv[3*c+1]) * (1.0f/3.0f);
        float z = (sv[3*a+2] + sv[3*b+2] + sv[3*c+2]) * (1.0f/3.0f);
        float n2 = x*x + y*y + z*z;
        g_src_bc[i]      = make_float4(x, y, z, 0.5f*n2);
        g_pts[NPTS + i]  = make_float4(x, y, z, n2);       // fwd loss as a "point"
        int ta = tf[i], tb = tf[FT + i], tc = tf[2*FT + i];
        float tx = (tv[3*ta+0] + tv[3*tb+0] + tv[3*tc+0]) * (1.0f/3.0f);
        float ty = (tv[3*ta+1] + tv[3*tb+1] + tv[3*tc+1]) * (1.0f/3.0f);
        float tz = (tv[3*ta+2] + tv[3*tb+2] + tv[3*tc+2]) * (1.0f/3.0f);
        g_tgt_bc[i] = make_float4(tx, ty, tz, 0.5f*(tx*tx + ty*ty + tz*tz));
    }
    if (i < NPTS) {
        int f = i >> 3;
        int a = sf[3*f+0], b = sf[3*f+1], c = sf[3*f+2];
        float r1 = sqrtf(r1u[i]);
        float r2 = r2u[i];
        float w1 = 1.0f - r1;
        float w2 = r1 * (1.0f - r2);
        float w3 = r1 * r2;
        float x = w1*sv[3*a+0] + w2*sv[3*b+0] + w3*sv[3*c+0];
        float y = w1*sv[3*a+1] + w2*sv[3*b+1] + w3*sv[3*c+1];
        float z = w1*sv[3*a+2] + w2*sv[3*b+2] + w3*sv[3*c+2];
        g_pts[i] = make_float4(x, y, z, x*x + y*y + z*z);
    }
}

// ---------------------------------------------------------------------------
// Kernel 2: target min over one slice — branchless. Covers 36864 points.
// grid = TGT_PG * SLICES : pg = b>>4, slice = b&15
// ---------------------------------------------------------------------------
__global__ void __launch_bounds__(RTPB) rev_tgt_kernel() {
    __shared__ ulonglong2 s_pk[SL];   // 4 KB
    int tid = threadIdx.x;
    int pg  = blockIdx.x >> 4;
    int sl  = blockIdx.x & 15;
    load_packed_slice(s_pk, g_tgt_bc, sl * SL, tid);
    __syncthreads();

    int i0 = pg * 256 + tid;
    int i1 = i0 + 128;
    float4 p0 = g_pts[i0], p1 = g_pts[i1];
    u64 ax = pk2(-p0.x, -p0.x), ay = pk2(-p0.y, -p0.y), az = pk2(-p0.z, -p0.z);
    u64 bx = pk2(-p1.x, -p1.x), by = pk2(-p1.y, -p1.y), bz = pk2(-p1.z, -p1.z);

    float mA0 = 1e30f, mA1 = 1e30f, mB0 = 1e30f, mB1 = 1e30f;
    #pragma unroll 8
    for (int t = 0; t < SL/2; t++) {
        ulonglong2 U = s_pk[2*t], V = s_pk[2*t+1];
        u64 dA = fma2(ax, U.x, fma2(ay, U.y, fma2(az, V.x, V.y)));
        u64 dB = fma2(bx, U.x, fma2(by, U.y, fma2(bz, V.x, V.y)));
        float e0, e1;
        upk2(dA, e0, e1); mA0 = fminf(mA0, e0); mA1 = fminf(mA1, e1);
        upk2(dB, e0, e1); mB0 = fminf(mB0, e0); mB1 = fminf(mB1, e1);
    }
    g_mteh[sl][i0] = fminf(mA0, mA1);
    g_mteh[sl][i1] = fminf(mB0, mB1);
}

// ---------------------------------------------------------------------------
// Kernel 3: source top-6 over one slice — exact two-stage.
// Stage 1: branchless chunk minima (CH=8), keep top-6 chunk mins.
// Stage 2: rescan the 6 selected chunks with full insertion.
// grid = SRC_PG * SLICES : pg = b>>4, slice = b&15
// ---------------------------------------------------------------------------
__global__ void __launch_bounds__(RTPB) rev_src_kernel() {
    __shared__ ulonglong2 s_pk[SL];   // 4 KB
    int tid = threadIdx.x;
    int pg  = blockIdx.x >> 4;
    int sl  = blockIdx.x & 15;
    int jb  = sl * SL;
    load_packed_slice(s_pk, g_src_bc, jb, tid);
    __syncthreads();

    int i0 = pg * 256 + tid;
    int i1 = i0 + 128;
    float4 p0 = g_pts[i0], p1 = g_pts[i1];
    u64 ax = pk2(-p0.x, -p0.x), ay = pk2(-p0.y, -p0.y), az = pk2(-p0.z, -p0.z);
    u64 bx = pk2(-p1.x, -p1.x), by = pk2(-p1.y, -p1.y), bz = pk2(-p1.z, -p1.z);

    // ---- Stage 1: top-6 of chunk minima ----
    float beA[6], beB[6]; int biA[6], biB[6];
    #pragma unroll
    for (int k = 0; k < 6; k++) {
        beA[k] = 1e30f; biA[k] = -1;
        beB[k] = 1e30f; biB[k] = -1;
    }
    for (int c = 0; c < NCH; c++) {
        float mA = 1e30f, mB = 1e30f;
        int base = CH * c;
        #pragma unroll
        for (int t = 0; t < CH/2; t++) {
            ulonglong2 U = s_pk[base + 2*t], V = s_pk[base + 2*t + 1];
            u64 dA = fma2(ax, U.x, fma2(ay, U.y, fma2(az, V.x, V.y)));
            u64 dB = fma2(bx, U.x, fma2(by, U.y, fma2(bz, V.x, V.y)));
            float e0, e1;
            upk2(dA, e0, e1); mA = fminf(mA, fminf(e0, e1));
            upk2(dB, e0, e1); mB = fminf(mB, fminf(e0, e1));
        }
        try_insert(mA, c, beA, biA);
        try_insert(mB, c, beB, biB);
    }

    // ---- Stage 2: rescan selected chunks (ascending chunk id for ties) ----
    int idsA[6], idsB[6];
    #pragma unroll
    for (int k = 0; k < 6; k++) { idsA[k] = biA[k]; idsB[k] = biB[k]; }
    #pragma unroll
    for (int a = 1; a < 6; a++)
        #pragma unroll
        for (int b2 = a; b2 > 0; b2--) {
            if (idsA[b2] < idsA[b2-1]) { int t = idsA[b2]; idsA[b2] = idsA[b2-1]; idsA[b2-1] = t; }
            if (idsB[b2] < idsB[b2-1]) { int t = idsB[b2]; idsB[b2] = idsB[b2-1]; idsB[b2-1] = t; }
        }
    #pragma unroll
    for (int k = 0; k < 6; k++) {
        beA[k] = 1e30f; biA[k] = -1;
        beB[k] = 1e30f; biB[k] = -1;
    }
    #pragma unroll
    for (int k = 0; k < 6; k++) {
        int base = CH * idsA[k];
        #pragma unroll
        for (int t = 0; t < CH/2; t++) {
            ulonglong2 U = s_pk[base + 2*t], V = s_pk[base + 2*t + 1];
            u64 dA = fma2(ax, U.x, fma2(ay, U.y, fma2(az, V.x, V.y)));
            float e0, e1; upk2(dA, e0, e1);
            int j = jb + base + 2*t;
            try_insert(e0, j,     beA, biA);
            try_insert(e1, j + 1, beA, biA);
        }
    }
    #pragma unroll
    for (int k = 0; k < 6; k++) {
        int base = CH * idsB[k];
        #pragma unroll
        for (int t = 0; t < CH/2; t++) {
            ulonglong2 U = s_pk[base + 2*t], V = s_pk[base + 2*t + 1];
            u64 dB = fma2(bx, U.x, fma2(by, U.y, fma2(bz, V.x, V.y)));
            float e0, e1; upk2(dB, e0, e1);
            int j = jb + base + 2*t;
            try_insert(e0, j,     beB, biB);
            try_insert(e1, j + 1, beB, biB);
        }
    }
    #pragma unroll
    for (int k = 0; k < 6; k++) {
        g_be[sl][i0][k] = beA[k];  g_bi[sl][i0][k] = biA[k];
        g_be[sl][i1][k] = beB[k];  g_bi[sl][i1][k] = biB[k];
    }
}

// ---------------------------------------------------------------------------
// Kernel 4: forward loss from extended target-min results
// ---------------------------------------------------------------------------
__global__ void fwd_sum_kernel(const float* __restrict__ probs) {
    int tid = threadIdx.x;
    int f   = blockIdx.x * TPB + tid;
    int i   = NPTS + f;
    float mte = 1e30f;
    #pragma unroll
    for (int s = 0; s < SLICES; s++) mte = fminf(mte, g_mteh[s][i]);
    float d = fmaxf(fmaf(2.0f, mte, g_pts[i].w), 0.0f);
    float contrib = probs[f] * d;

    __shared__ float red[TPB];
    red[tid] = contrib;
    __syncthreads();
    #pragma unroll
    for (int s = TPB/2; s > 0; s >>= 1) {
        if (tid < s) red[tid] += red[tid + s];
        __syncthreads();
    }
    if (tid == 0) g_fwd_partial[blockIdx.x] = red[0];
}

// ---------------------------------------------------------------------------
// Kernel 5: merge 16 slice lists, self-exclusion, per-point value, reduce.
// ---------------------------------------------------------------------------
__device__ __forceinline__ void merge6(const float* ea, const int* ia,
                                       const float* eb, const int* ib,
                                       float* eo, int* io) {
    int a = 0, b = 0;
    #pragma unroll
    for (int k = 0; k < 6; k++) {
        float va = ea[a], vb = eb[b];
        bool tA = (va <= vb);          // left list = lower indices wins ties
        eo[k] = tA ? va : vb;
        io[k] = tA ? ia[a] : ib[b];
        a += tA ? 1 : 0;
        b += tA ? 0 : 1;
    }
}

__global__ void merge_kernel(const float* __restrict__ probs) {
    int tid = threadIdx.x;
    int i   = blockIdx.x * TPB + tid;
    int sface = i >> 3;

    float me[6]; int mi[6];
    #pragma unroll
    for (int k = 0; k < 6; k++) { me[k] = g_be[0][i][k]; mi[k] = g_bi[0][i][k]; }
    #pragma unroll
    for (int s = 1; s < SLICES; s++) {
        float eb[6], tmp[6]; int ib[6], tmpi[6];
        #pragma unroll
        for (int k = 0; k < 6; k++) { eb[k] = g_be[s][i][k]; ib[k] = g_bi[s][i][k]; }
        merge6(me, mi, eb, ib, tmp, tmpi);
        #pragma unroll
        for (int k = 0; k < 6; k++) { me[k] = tmp[k]; mi[k] = tmpi[k]; }
    }

    float pw = g_pts[i].w;
    int selfpos = 6;
    #pragma unroll
    for (int k = 0; k < 6; k++) if (mi[k] == sface) selfpos = k;
    float s5 = 0.0f;
    #pragma unroll
    for (int k = 0; k < 6; k++) {
        bool inc = (k != selfpos) && (k < 5 || selfpos <= 5);
        if (inc) {
            float d = fmaxf(fmaf(2.0f, me[k], pw), 0.0f);
            s5 += probs[mi[k]] * d;
        }
    }
    float mte = 1e30f;
    #pragma unroll
    for (int s = 0; s < SLICES; s++) mte = fminf(mte, g_mteh[s][i]);
    float pp   = probs[sface];
    float mind = fmaxf(fmaf(2.0f, mte, pw), 0.0f);
    float val  = fmaf(pp, mind, (1.0f - pp) * (s5 * 0.2f));

    __shared__ float red[TPB];
    red[tid] = val;
    __syncthreads();
    #pragma unroll
    for (int s = TPB/2; s > 0; s >>= 1) {
        if (tid < s) red[tid] += red[tid + s];
        __syncthreads();
    }
    if (tid == 0) g_rev_partial[blockIdx.x] = red[0];
}

// ---------------------------------------------------------------------------
// Kernel 6: deterministic final reduction
// ---------------------------------------------------------------------------
__global__ void final_kernel(float* __restrict__ out) {
    __shared__ float red[TPB];
    int t = threadIdx.x;
    float v = 0.0f;
    if (t < MRG_BLK)  v += g_rev_partial[t];
    if (t < FSUM_BLK) v += g_fwd_partial[t];
    red[t] = v;
    __syncthreads();
    #pragma unroll
    for (int s = TPB/2; s > 0; s >>= 1) {
        if (t < s) red[t] += red[t + s];
        __syncthreads();
    }
    if (t == 0) out[0] = red[0];
}

extern "C" void kernel_launch(void* const* d_in, const int* in_sizes, int n_in,
                              void* d_out, int out_size) {
    const float* sv    = (const float*)d_in[0];
    const int*   sf    = (const int*)  d_in[1];
    const float* tv    = (const float*)d_in[2];
    const int*   tf    = (const int*)  d_in[3];
    const float* probs = (const float*)d_in[4];
    const float* r1u   = (const float*)d_in[5];
    const float* r2u   = (const float*)d_in[6];

    prep_kernel   <<<NPTS / TPB, TPB>>>(sv, sf, tv, tf, r1u, r2u);
    rev_tgt_kernel<<<TGT_PG * SLICES, RTPB>>>();   // 2304 blocks
    fwd_sum_kernel<<<FSUM_BLK, TPB>>>(probs);
    rev_src_kernel<<<SRC_PG * SLICES, RTPB>>>();   // 2048 blocks (4th: ncu slot)
    merge_kernel  <<<MRG_BLK, TPB>>>(probs);
    final_kernel  <<<1, TPB>>>((float*)d_out);
}

// round 9
// speedup vs baseline: 1.3674x; 1.3674x over previous
#include <cuda_runtime.h>

#define FS 4096
#define FT 4096
#define NPTS (FS * 8)            // 32768 sample points
#define NPE  (NPTS + FS)         // + 4096 src barycenters = 36864
#define TPB 256
#define RTPB 128
#define SLICES 8
#define SL 512                   // candidates per slice
#define CH 8                     // chunk size
#define NCH (SL / CH)            // 64 chunks per slice
#define SRC_PG (NPTS / (RTPB * 2))   // 128 point-groups (256 pts each)
#define TGT_PG (NPE  / (RTPB * 2))   // 144 point-groups
#define SRC_BLKS (SRC_PG * SLICES)   // 1024
#define TGT_BLKS (TGT_PG * SLICES)   // 1152
#define MRG_BLK (NPTS / TPB)         // 128
#define FSUM_BLK (FS / TPB)          // 16
#define PART_BLK (MRG_BLK + FSUM_BLK) // 144

typedef unsigned long long u64;

// Scratch (allocation-free: __device__ globals)
__device__ float4 g_src_bc[FS];        // xyz, w = 0.5*|bc|^2 (candidate form)
__device__ float4 g_tgt_bc[FT];        // xyz, w = 0.5*|bc|^2
__device__ float4 g_pts[NPE];          // xyz, w = |p|^2 (full norm)
__device__ float  g_be[SLICES][NPTS][6];
__device__ int    g_bi[SLICES][NPTS][6];
__device__ float  g_mteh[SLICES][NPE];
__device__ float  g_partial[PART_BLK];

// ---- packed f32x2 helpers (sm_103a) ---------------------------------------
__device__ __forceinline__ u64 pk2(float a, float b) {
    u64 r; asm("mov.b64 %0,{%1,%2};" : "=l"(r) : "f"(a), "f"(b)); return r;
}
__device__ __forceinline__ u64 fma2(u64 a, u64 b, u64 c) {
    u64 d; asm("fma.rn.f32x2 %0,%1,%2,%3;" : "=l"(d) : "l"(a), "l"(b), "l"(c)); return d;
}
__device__ __forceinline__ void upk2(u64 d, float& x, float& y) {
    asm("mov.b64 {%0,%1},%2;" : "=f"(x), "=f"(y) : "l"(d));
}

// ascending insert, strict < keeps earlier (lower-index) candidate on ties
__device__ __forceinline__ void try_insert(float e, int j, float be[6], int bi[6]) {
    if (e < be[5]) {
        be[5] = e; bi[5] = j;
        #pragma unroll
        for (int k = 5; k > 0; --k) {
            if (be[k] < be[k-1]) {
                float te = be[k]; be[k] = be[k-1]; be[k-1] = te;
                int   ti = bi[k]; bi[k] = bi[k-1]; bi[k-1] = ti;
            }
        }
    }
}

// Pack SL candidates (pair-interleaved) from g[off..off+SL) into smem.
__device__ __forceinline__ void load_packed_slice(ulonglong2* s, const float4* g,
                                                  int off, int tid) {
    for (int t = tid; t < SL/2; t += RTPB) {
        float4 a = g[off + 2*t], b = g[off + 2*t + 1];
        ulonglong2 u0, u1;
        u0.x = pk2(a.x, b.x); u0.y = pk2(a.y, b.y);
        u1.x = pk2(a.z, b.z); u1.y = pk2(a.w, b.w);
        s[2*t]   = u0;
        s[2*t+1] = u1;
    }
}

// ---------------------------------------------------------------------------
// Kernel 1: barycenters + sampled points (+ barycenters-as-points)
// ---------------------------------------------------------------------------
__global__ void prep_kernel(const float* __restrict__ sv, const int* __restrict__ sf,
                            const float* __restrict__ tv, const int* __restrict__ tf,
                            const float* __restrict__ r1u, const float* __restrict__ r2u) {
    int i = blockIdx.x * blockDim.x + threadIdx.x;
    if (i < FS) {
        int a = sf[3*i+0], b = sf[3*i+1], c = sf[3*i+2];
        float x = (sv[3*a+0] + sv[3*b+0] + sv[3*c+0]) * (1.0f/3.0f);
        float y = (sv[3*a+1] + sv[3*b+1] + sv[3*c+1]) * (1.0f/3.0f);
        float z = (sv[3*a+2] + sv[3*b+2] + sv[3*c+2]) * (1.0f/3.0f);
        float n2 = x*x + y*y + z*z;
        g_src_bc[i]      = make_float4(x, y, z, 0.5f*n2);
        g_pts[NPTS + i]  = make_float4(x, y, z, n2);       // fwd loss as a "point"
        int ta = tf[i], tb = tf[FT + i], tc = tf[2*FT + i];
        float tx = (tv[3*ta+0] + tv[3*tb+0] + tv[3*tc+0]) * (1.0f/3.0f);
        float ty = (tv[3*ta+1] + tv[3*tb+1] + tv[3*tc+1]) * (1.0f/3.0f);
        float tz = (tv[3*ta+2] + tv[3*tb+2] + tv[3*tc+2]) * (1.0f/3.0f);
        g_tgt_bc[i] = make_float4(tx, ty, tz, 0.5f*(tx*tx + ty*ty + tz*tz));
    }
    if (i < NPTS) {
        int f = i >> 3;
        int a = sf[3*f+0], b = sf[3*f+1], c = sf[3*f+2];
        float r1 = sqrtf(r1u[i]);
        float r2 = r2u[i];
        float w1 = 1.0f - r1;
        float w2 = r1 * (1.0f - r2);
        float w3 = r1 * r2;
        float x = w1*sv[3*a+0] + w2*sv[3*b+0] + w3*sv[3*c+0];
        float y = w1*sv[3*a+1] + w2*sv[3*b+1] + w3*sv[3*c+1];
        float z = w1*sv[3*a+2] + w2*sv[3*b+2] + w3*sv[3*c+2];
        g_pts[i] = make_float4(x, y, z, x*x + y*y + z*z);
    }
}

// ---------------------------------------------------------------------------
// Kernel 2 (fused): src top-6 (blocks 0..SRC_BLKS) + tgt min (rest).
// Src blocks first: they're heavier (stage-2 + inserts), tgt fills the tail.
// ---------------------------------------------------------------------------
__global__ void __launch_bounds__(RTPB) rev_kernel() {
    __shared__ ulonglong2 s_pk[SL];   // 8 KB
    int tid = threadIdx.x;
    int b   = blockIdx.x;

    if (b < SRC_BLKS) {
        // ================= source top-6, exact two-stage =================
        int pg  = b >> 3;
        int sl  = b & 7;
        int jb  = sl * SL;
        load_packed_slice(s_pk, g_src_bc, jb, tid);
        __syncthreads();

        int i0 = pg * 256 + tid;
        int i1 = i0 + 128;
        float4 p0 = g_pts[i0], p1 = g_pts[i1];
        u64 ax = pk2(-p0.x, -p0.x), ay = pk2(-p0.y, -p0.y), az = pk2(-p0.z, -p0.z);
        u64 bx = pk2(-p1.x, -p1.x), by = pk2(-p1.y, -p1.y), bz = pk2(-p1.z, -p1.z);

        // ---- Stage 1: top-6 of chunk minima (CH=8) ----
        float beA[6], beB[6]; int biA[6], biB[6];
        #pragma unroll
        for (int k = 0; k < 6; k++) {
            beA[k] = 1e30f; biA[k] = -1;
            beB[k] = 1e30f; biB[k] = -1;
        }
        for (int c = 0; c < NCH; c++) {
            float mA = 1e30f, mB = 1e30f;
            int base = CH * c;
            #pragma unroll
            for (int t = 0; t < CH/2; t++) {
                ulonglong2 U = s_pk[base + 2*t], V = s_pk[base + 2*t + 1];
                u64 dA = fma2(ax, U.x, fma2(ay, U.y, fma2(az, V.x, V.y)));
                u64 dB = fma2(bx, U.x, fma2(by, U.y, fma2(bz, V.x, V.y)));
                float e0, e1;
                upk2(dA, e0, e1); mA = fminf(mA, fminf(e0, e1));
                upk2(dB, e0, e1); mB = fminf(mB, fminf(e0, e1));
            }
            try_insert(mA, c, beA, biA);
            try_insert(mB, c, beB, biB);
        }

        // ---- Stage 2: rescan selected chunks (ascending id for ties) ----
        int idsA[6], idsB[6];
        #pragma unroll
        for (int k = 0; k < 6; k++) { idsA[k] = biA[k]; idsB[k] = biB[k]; }
        #pragma unroll
        for (int a = 1; a < 6; a++)
            #pragma unroll
            for (int b2 = a; b2 > 0; b2--) {
                if (idsA[b2] < idsA[b2-1]) { int t = idsA[b2]; idsA[b2] = idsA[b2-1]; idsA[b2-1] = t; }
                if (idsB[b2] < idsB[b2-1]) { int t = idsB[b2]; idsB[b2] = idsB[b2-1]; idsB[b2-1] = t; }
            }
        #pragma unroll
        for (int k = 0; k < 6; k++) {
            beA[k] = 1e30f; biA[k] = -1;
            beB[k] = 1e30f; biB[k] = -1;
        }
        #pragma unroll
        for (int k = 0; k < 6; k++) {
            int base = CH * idsA[k];
            #pragma unroll
            for (int t = 0; t < CH/2; t++) {
                ulonglong2 U = s_pk[base + 2*t], V = s_pk[base + 2*t + 1];
                u64 dA = fma2(ax, U.x, fma2(ay, U.y, fma2(az, V.x, V.y)));
                float e0, e1; upk2(dA, e0, e1);
                int j = jb + base + 2*t;
                try_insert(e0, j,     beA, biA);
                try_insert(e1, j + 1, beA, biA);
            }
        }
        #pragma unroll
        for (int k = 0; k < 6; k++) {
            int base = CH * idsB[k];
            #pragma unroll
            for (int t = 0; t < CH/2; t++) {
                ulonglong2 U = s_pk[base + 2*t], V = s_pk[base + 2*t + 1];
                u64 dB = fma2(bx, U.x, fma2(by, U.y, fma2(bz, V.x, V.y)));
                float e0, e1; upk2(dB, e0, e1);
                int j = jb + base + 2*t;
                try_insert(e0, j,     beB, biB);
                try_insert(e1, j + 1, beB, biB);
            }
        }
        #pragma unroll
        for (int k = 0; k < 6; k++) {
            g_be[sl][i0][k] = beA[k];  g_bi[sl][i0][k] = biA[k];
            g_be[sl][i1][k] = beB[k];  g_bi[sl][i1][k] = biB[k];
        }
    } else {
        // ================= target min, branchless =================
        b -= SRC_BLKS;
        int pg = b >> 3;
        int sl = b & 7;
        load_packed_slice(s_pk, g_tgt_bc, sl * SL, tid);
        __syncthreads();

        int i0 = pg * 256 + tid;
        int i1 = i0 + 128;
        float4 p0 = g_pts[i0], p1 = g_pts[i1];
        u64 ax = pk2(-p0.x, -p0.x), ay = pk2(-p0.y, -p0.y), az = pk2(-p0.z, -p0.z);
        u64 bx = pk2(-p1.x, -p1.x), by = pk2(-p1.y, -p1.y), bz = pk2(-p1.z, -p1.z);

        float mA0 = 1e30f, mA1 = 1e30f, mB0 = 1e30f, mB1 = 1e30f;
        #pragma unroll 8
        for (int t = 0; t < SL/2; t++) {
            ulonglong2 U = s_pk[2*t], V = s_pk[2*t+1];
            u64 dA = fma2(ax, U.x, fma2(ay, U.y, fma2(az, V.x, V.y)));
            u64 dB = fma2(bx, U.x, fma2(by, U.y, fma2(bz, V.x, V.y)));
            float e0, e1;
            upk2(dA, e0, e1); mA0 = fminf(mA0, e0); mA1 = fminf(mA1, e1);
            upk2(dB, e0, e1); mB0 = fminf(mB0, e0); mB1 = fminf(mB1, e1);
        }
        g_mteh[sl][i0] = fminf(mA0, mA1);
        g_mteh[sl][i1] = fminf(mB0, mB1);
    }
}

// ---------------------------------------------------------------------------
// Kernel 3 (fused): merge 8 slice lists + per-point value (blocks 0..127),
// forward loss per face (blocks 128..143). Block-reduced partials.
// ---------------------------------------------------------------------------
__device__ __forceinline__ void merge6(const float* ea, const int* ia,
                                       const float* eb, const int* ib,
                                       float* eo, int* io) {
    int a = 0, b = 0;
    #pragma unroll
    for (int k = 0; k < 6; k++) {
        float va = ea[a], vb = eb[b];
        bool tA = (va <= vb);          // left list = lower indices wins ties
        eo[k] = tA ? va : vb;
        io[k] = tA ? ia[a] : ib[b];
        a += tA ? 1 : 0;
        b += tA ? 0 : 1;
    }
}

__global__ void merge_kernel(const float* __restrict__ probs) {
    int tid = threadIdx.x;
    float val;

    if (blockIdx.x < MRG_BLK) {
        int i     = blockIdx.x * TPB + tid;
        int sface = i >> 3;

        float me[6]; int mi[6];
        #pragma unroll
        for (int k = 0; k < 6; k++) { me[k] = g_be[0][i][k]; mi[k] = g_bi[0][i][k]; }
        #pragma unroll
        for (int s = 1; s < SLICES; s++) {
            float eb[6], tmp[6]; int ib[6], tmpi[6];
            #pragma unroll
            for (int k = 0; k < 6; k++) { eb[k] = g_be[s][i][k]; ib[k] = g_bi[s][i][k]; }
            merge6(me, mi, eb, ib, tmp, tmpi);
            #pragma unroll
            for (int k = 0; k < 6; k++) { me[k] = tmp[k]; mi[k] = tmpi[k]; }
        }

        float pw = g_pts[i].w;
        int selfpos = 6;
        #pragma unroll
        for (int k = 0; k < 6; k++) if (mi[k] == sface) selfpos = k;
        float s5 = 0.0f;
        #pragma unroll
        for (int k = 0; k < 6; k++) {
            bool inc = (k != selfpos) && (k < 5 || selfpos <= 5);
            if (inc) {
                float d = fmaxf(fmaf(2.0f, me[k], pw), 0.0f);
                s5 += probs[mi[k]] * d;
            }
        }
        float mte = 1e30f;
        #pragma unroll
        for (int s = 0; s < SLICES; s++) mte = fminf(mte, g_mteh[s][i]);
        float pp   = probs[sface];
        float mind = fmaxf(fmaf(2.0f, mte, pw), 0.0f);
        val = fmaf(pp, mind, (1.0f - pp) * (s5 * 0.2f));
    } else {
        // forward loss: one face per thread
        int f = (blockIdx.x - MRG_BLK) * TPB + tid;
        int i = NPTS + f;
        float mte = 1e30f;
        #pragma unroll
        for (int s = 0; s < SLICES; s++) mte = fminf(mte, g_mteh[s][i]);
        float d = fmaxf(fmaf(2.0f, mte, g_pts[i].w), 0.0f);
        val = probs[f] * d;
    }

    __shared__ float red[TPB];
    red[tid] = val;
    __syncthreads();
    #pragma unroll
    for (int s = TPB/2; s > 0; s >>= 1) {
        if (tid < s) red[tid] += red[tid + s];
        __syncthreads();
    }
    if (tid == 0) g_partial[blockIdx.x] = red[0];
}

// ---------------------------------------------------------------------------
// Kernel 4: deterministic final reduction
// ---------------------------------------------------------------------------
__global__ void final_kernel(float* __restrict__ out) {
    __shared__ float red[TPB];
    int t = threadIdx.x;
    float v = (t < PART_BLK) ? g_partial[t] : 0.0f;
    red[t] = v;
    __syncthreads();
    #pragma unroll
    for (int s = TPB/2; s > 0; s >>= 1) {
        if (t < s) red[t] += red[t + s];
        __syncthreads();
    }
    if (t == 0) out[0] = red[0];
}

extern "C" void kernel_launch(void* const* d_in, const int* in_sizes, int n_in,
                              void* d_out, int out_size) {
    const float* sv    = (const float*)d_in[0];
    const int*   sf    = (const int*)  d_in[1];
    const float* tv    = (const float*)d_in[2];
    const int*   tf    = (const int*)  d_in[3];
    const float* probs = (const float*)d_in[4];
    const float* r1u   = (const float*)d_in[5];
    const float* r2u   = (const float*)d_in[6];

    prep_kernel <<<NPTS / TPB, TPB>>>(sv, sf, tv, tf, r1u, r2u);
    rev_kernel  <<<SRC_BLKS + TGT_BLKS, RTPB>>>();   // 2176 blocks, fused
    merge_kernel<<<PART_BLK, TPB>>>(probs);          // 144 blocks, fwd folded in
    final_kernel<<<1, TPB>>>((float*)d_out);
}